// round 5
// baseline (speedup 1.0000x reference)
#include <cuda_runtime.h>

// CrossAttentionConditionInjection — analytic collapse, 2 kernels.
//
// K/V come from one condition token broadcast across seq: every score row is
// constant => softmax weights are exactly 1/S (S=2048 pow2) => attn == v1.
//   out[b,s,:] = Wo @ (Wv @ cond[b] + bv) + bo     for every s.
//
// R5 structure (evidence: fused-1-kernel was SLOWER; phases are cycle-bound):
//   K1: split-K(4) partial dots of Wv@cond  -> g_part   (short critical path)
//   K2: per-block: 16 rows of o1 = Wo@(Σparts+bv)+bo, then broadcast those
//       rows across all s. No grid sync; Wo reads overlap output stores.

#define BDIM 1024
#define NB   2
#define NS   2048

// part[c][b][d] : c=K-chunk 0..3. float4-aligned.
__device__ float4 g_part4[4 * NB * BDIM / 4];

// ---------------------------------------------------------------------------
// K1: 8192 warps; warp tau handles (row t = tau>>2, K-chunk c = tau&3).
// Each lane: 2 float4 of W and cond (chunk = 1KB of the row). bv folded into
// chunk 0. 256 blocks x 1024 threads.
// ---------------------------------------------------------------------------
__global__ void __launch_bounds__(1024) k1_partial(const float* __restrict__ Wv,
                                                   const float* __restrict__ cond,
                                                   const float* __restrict__ bv) {
    int tau  = (blockIdx.x * 1024 + threadIdx.x) >> 5;   // 0..8191
    int lane = threadIdx.x & 31;
    int t    = tau >> 2;                                 // 0..2047
    int c    = tau & 3;
    int b    = t >> 10;
    int d    = t & (BDIM - 1);

    const float4* W4 = reinterpret_cast<const float4*>(Wv + (size_t)d * BDIM) + c * 64;
    const float4* x4 = reinterpret_cast<const float4*>(cond + (size_t)b * BDIM) + c * 64;

    float4 w0 = W4[lane], w1 = W4[lane + 32];
    float4 x0 = x4[lane], x1 = x4[lane + 32];
    float s = w0.x * x0.x + w0.y * x0.y + w0.z * x0.z + w0.w * x0.w
            + w1.x * x1.x + w1.y * x1.y + w1.z * x1.z + w1.w * x1.w;
#pragma unroll
    for (int off = 16; off; off >>= 1)
        s += __shfl_xor_sync(0xffffffffu, s, off);
    if (lane == 0) {
        float* part = reinterpret_cast<float*>(g_part4);
        part[c * (NB * BDIM) + t] = (c == 0) ? (s + bv[d]) : s;
    }
}

// ---------------------------------------------------------------------------
// K2: 128 blocks x 256 threads. Block = (b, dchunk of 16 d's).
// Step A: 8 warps x 2 rows: o1[d] = dot(Wo[d,:], v1[b,:]) + bo[d], where
//         v1 is reassembled on the fly from the 4 partials (L1/L2-hot).
// Step B: broadcast: each thread owns one float4 column of the 64B chunk and
//         streams it to 2048/64 x ... all s rows (32 STG.128 per thread).
// ---------------------------------------------------------------------------
__global__ void __launch_bounds__(256) k2_fused(const float* __restrict__ Wo,
                                                const float* __restrict__ bo,
                                                float4* __restrict__ out) {
    __shared__ float4 s_o1[4];                 // this block's 16 o1 floats

    int b  = blockIdx.x >> 6;                  // 0..1
    int d0 = (blockIdx.x & 63) * 16;           // first of 16 d rows
    int warp = threadIdx.x >> 5;
    int lane = threadIdx.x & 31;

    // ---- Step A ----
    {
        int r = d0 + warp * 2;                 // this warp's two rows
        const float4* W0 = reinterpret_cast<const float4*>(Wo + (size_t)r * BDIM);
        const float4* W1 = W0 + (BDIM / 4);
        const float4* P  = g_part4;            // [c][b][j] : c*512 + b*256 + j
        float s0 = 0.f, s1 = 0.f;
#pragma unroll
        for (int j = 0; j < 8; ++j) {
            int xi = j * 32 + lane;
            float4 x  = P[          b * 256 + xi];
            float4 p1 = P[1 * 512 + b * 256 + xi];
            float4 p2 = P[2 * 512 + b * 256 + xi];
            float4 p3 = P[3 * 512 + b * 256 + xi];
            x.x += p1.x + p2.x + p3.x;  x.y += p1.y + p2.y + p3.y;
            x.z += p1.z + p2.z + p3.z;  x.w += p1.w + p2.w + p3.w;
            float4 w0 = W0[xi], w1 = W1[xi];
            s0 += w0.x * x.x + w0.y * x.y + w0.z * x.z + w0.w * x.w;
            s1 += w1.x * x.x + w1.y * x.y + w1.z * x.z + w1.w * x.w;
        }
#pragma unroll
        for (int off = 16; off; off >>= 1) {
            s0 += __shfl_xor_sync(0xffffffffu, s0, off);
            s1 += __shfl_xor_sync(0xffffffffu, s1, off);
        }
        if (lane == 0) {
            float* so = reinterpret_cast<float*>(s_o1);
            so[warp * 2]     = s0 + bo[r];
            so[warp * 2 + 1] = s1 + bo[r + 1];
        }
    }
    __syncthreads();

    // ---- Step B ----
    int sl = threadIdx.x >> 2;                 // 0..63 : s offset within stripe
    int c  = threadIdx.x & 3;                  // float4 column within 64B chunk
    float4 val = s_o1[c];
    size_t base = ((size_t)b * NS) * (BDIM / 4) + (d0 >> 2) + c;
#pragma unroll
    for (int it = 0; it < NS / 64; ++it) {     // 32 stores per thread
        int s = it * 64 + sl;
        out[base + (size_t)s * (BDIM / 4)] = val;
    }
}

extern "C" void kernel_launch(void* const* d_in, const int* in_sizes, int n_in,
                              void* d_out, int out_size) {
    // metadata order: hidden_states, condition, Wq, bq, Wk, bk, Wv, bv, Wo, bo
    const float* cond = (const float*)d_in[1];
    const float* Wv   = (const float*)d_in[6];
    const float* bv   = (const float*)d_in[7];
    const float* Wo   = (const float*)d_in[8];
    const float* bo   = (const float*)d_in[9];

    k1_partial<<<256, 1024>>>(Wv, cond, bv);
    k2_fused<<<128, 256>>>(Wo, bo, (float4*)d_out);
}

// round 7
// speedup vs baseline: 1.1693x; 1.1693x over previous
#include <cuda_runtime.h>

// CrossAttentionConditionInjection — analytic collapse, 3 kernels.
//
// K/V come from one condition token broadcast across seq: every score row is
// constant => softmax weights are exactly 1/S (S=2048, power of two)
// => attn == v1 broadcast. Entire op:
//   out[b,s,:] = Wo @ (Wv @ cond[b] + bv) + bo   (same vector for every s)
//
// R7 = resubmission of the R6 experiment (container flake, never ran):
// bench dur == sum of COLD kernel times across all rounds => weights are
// evicted from L2 every replay. Suspect: 16MB of evict-normal output stores.
// Fix: __stcs (evict-first) streaming stores in the broadcast so the 8MB of
// weights stay L2-resident across graph replays.

#define BDIM 1024   // D
#define NB   2      // B
#define NS   2048   // S

__device__ float g_v1[NB * BDIM];
__device__ float g_o1[NB * BDIM];

// ---------------------------------------------------------------------------
// Warp-per-row matvec: y[b*D+d] = dot(W[d,:], x[b,:]) + bias[d].
// 2048 rows, warp per row; lane covers 8 float4 of the 4KB row, issued in
// two interleaved batches of 4 (MLP>=8 in flight, moderate register peak).
// ---------------------------------------------------------------------------
__device__ __forceinline__ void mv_body(const float* __restrict__ W,
                                        const float* __restrict__ x,
                                        const float* __restrict__ bias,
                                        float* __restrict__ y) {
    int w    = (blockIdx.x * blockDim.x + threadIdx.x) >> 5;   // 0..2047
    int lane = threadIdx.x & 31;
    int b = w >> 10;
    int d = w & (BDIM - 1);

    const float4* W4 = reinterpret_cast<const float4*>(W + (size_t)d * BDIM);
    const float4* x4 = reinterpret_cast<const float4*>(x + (size_t)b * BDIM);

    float sum = 0.f;
#pragma unroll
    for (int h = 0; h < 2; ++h) {
        float4 wv[4], xv[4];
#pragma unroll
        for (int i = 0; i < 4; ++i) wv[i] = W4[lane + (h * 4 + i) * 32];
#pragma unroll
        for (int i = 0; i < 4; ++i) xv[i] = x4[lane + (h * 4 + i) * 32];
#pragma unroll
        for (int i = 0; i < 4; ++i)
            sum += wv[i].x * xv[i].x + wv[i].y * xv[i].y
                 + wv[i].z * xv[i].z + wv[i].w * xv[i].w;
    }
#pragma unroll
    for (int off = 16; off; off >>= 1)
        sum += __shfl_xor_sync(0xffffffffu, sum, off);
    if (lane == 0) y[w] = sum + bias[d];
}

__global__ void __launch_bounds__(256) mv_stage1(const float* __restrict__ Wv,
                                                 const float* __restrict__ cond,
                                                 const float* __restrict__ bv) {
    mv_body(Wv, cond, bv, g_v1);
}

__global__ void __launch_bounds__(256) mv_stage2(const float* __restrict__ Wo,
                                                 const float* __restrict__ bo) {
    mv_body(Wo, g_v1, bo, g_o1);
}

// ---------------------------------------------------------------------------
// Broadcast: out[b,s,:] = o1[b,:]. One float4 STREAMING store per thread
// (__stcs = evict-first): keeps the 16MB output from thrashing the weights
// out of L2 between graph replays. Source o1 (8KB) is L1/L2-hot.
// ---------------------------------------------------------------------------
__global__ void __launch_bounds__(512) bcast_kernel(float4* __restrict__ out) {
    const float4* o1 = reinterpret_cast<const float4*>(g_o1);
    int i  = blockIdx.x * blockDim.x + threadIdx.x;
    int b  = i >> 19;          // / (S*D/4)
    int d4 = i & 255;          // % (D/4)
    __stcs(out + i, o1[(b << 8) + d4]);
}

extern "C" void kernel_launch(void* const* d_in, const int* in_sizes, int n_in,
                              void* d_out, int out_size) {
    // metadata order: hidden_states, condition, Wq, bq, Wk, bk, Wv, bv, Wo, bo
    const float* cond = (const float*)d_in[1];
    const float* Wv   = (const float*)d_in[6];
    const float* bv   = (const float*)d_in[7];
    const float* Wo   = (const float*)d_in[8];
    const float* bo   = (const float*)d_in[9];
    float*       out  = (float*)d_out;

    mv_stage1<<<256, 256>>>(Wv, cond, bv);
    mv_stage2<<<256, 256>>>(Wo, bo);
    bcast_kernel<<<(NB * NS * BDIM / 4) / 512, 512>>>((float4*)out);
}